// round 9
// baseline (speedup 1.0000x reference)
#include <cuda_runtime.h>
#include <math.h>

// -----------------------------------------------------------------------------
// NeuralSplineFourierFilter — fused persistent kernel, WRITE-THROUGH stores.
//
// Model (fits all 8 prior rounds): bound = total LTS-side traffic including
// DRAM fills + writebacks (~230MB/replay at ~10-11 TB/s LTS cap -> ~29us).
// x (64MB) and out (64MB) thrash each other in 126MB L2 under any allocating
// store policy. Fix: __stwt stores write through WITHOUT claiming L2 lines ->
// x becomes fully L2-resident across graph replays -> steady state:
//   reads  = 64MB of L2 HITS (no DRAM fills)
//   writes = 64MB write-through to DRAM
// Total LTS bytes drop ~230MB -> ~130-190MB; DRAM -> writes only.
//
// Everything else identical to the 29.2us best (r5 structure): 2048-cell
// linear-interp table (16KB smem, rel_err 1.4e-6), 912 blocks x 256, 4x float4.
// -----------------------------------------------------------------------------

#define NSFF_T 2048
#define NSFF_RSQRT3F 0.57735026918962576f

__device__ __forceinline__ float nsff_spline_eval(
    float xe, const float* __restrict__ sak, const float (*__restrict__ dP)[4]) {
    float xp = fminf(fmaxf(xe * NSFF_RSQRT3F, 0.0f), 0.9999f);
    int i = (xp >= sak[4]) + (xp >= sak[5]) + (xp >= sak[6])
          + (xp >= sak[7]) + (xp >= sak[8]) + (xp >= sak[9]);
    float u = xp - sak[3 + i];
    return fmaf(fmaf(fmaf(dP[i][3], u, dP[i][2]), u, dP[i][1]), u, dP[i][0]);
}

__device__ __forceinline__ float nsff_lookup(float xx, const float2* __restrict__ tab) {
    float y = xx * (float)NSFF_T;     // x in [0,1) -> y in [0,2048)
    int j = (int)y;
    float t = y - (float)j;
    float2 c = tab[j];
    return fmaf(t, c.y, c.x);
}

__global__ void __launch_bounds__(256, 6)
nsff_fused_kernel(const float* __restrict__ x,
                  const float* __restrict__ a,
                  const float* __restrict__ W1,
                  const float* __restrict__ b1,
                  const float* __restrict__ W2,
                  const float* __restrict__ b2,
                  const float* __restrict__ Ww,
                  const float* __restrict__ bw,
                  const float* __restrict__ Wk,
                  const float* __restrict__ bk,
                  float* __restrict__ out, int n4) {
    __shared__ float net1[32];
    __shared__ float net2[32];
    __shared__ float sw[9];
    __shared__ float skraw[7];
    __shared__ float sak[14];
    __shared__ float sc[10];
    __shared__ float dP[7][4];
    __shared__ __align__(8) float2 tab[NSFF_T];

    const int tid = threadIdx.x;

    // ---- tiny MLP (warp 0) ----
    if (tid < 32) {
        float av = a[0];
        net1[tid] = sinf(av * W1[tid] + b1[tid]);
    }
    __syncthreads();
    if (tid < 32) {
        float acc = b2[tid];
#pragma unroll
        for (int j = 0; j < 32; j++) acc += net1[j] * W2[j * 32 + tid];
        net2[tid] = sinf(acc);
    }
    __syncthreads();
    if (tid < 9) {
        float s = bw[tid];
#pragma unroll
        for (int j = 0; j < 32; j++) s += net2[j] * Ww[j * 9 + tid];
        sw[tid] = s;
    }
    if (tid < 7) {
        float s = bk[tid];
#pragma unroll
        for (int j = 0; j < 32; j++) s += net2[j] * Wk[j * 7 + tid];
        skraw[tid] = s;
    }
    __syncthreads();

    // ---- softmax + cumsum -> knot vector; control points (lane 0) ----
    if (tid == 0) {
        float m = skraw[0];
#pragma unroll
        for (int j = 1; j < 7; j++) m = fmaxf(m, skraw[j]);
        float e[7];
        float tot = 0.0f;
#pragma unroll
        for (int j = 0; j < 7; j++) { e[j] = expf(skraw[j] - m); tot += e[j]; }
        float inv = 1.0f / tot;

        sak[0] = sak[1] = sak[2] = 0.0f;
        sak[3] = 0.0f;
        float cum = 0.0f;
#pragma unroll
        for (int j = 0; j < 7; j++) { cum += e[j] * inv; sak[4 + j] = cum; }
        sak[11] = sak[12] = sak[13] = 1.0f;

        sc[0] = 0.0f;
#pragma unroll
        for (int j = 0; j < 9; j++) sc[1 + j] = sw[j];
    }
    __syncthreads();

    // ---- symbolic de Boor per interval k = 3 + lane, in u = xp - ak[k] ----
    if (tid < 7) {
        const int k = 3 + tid;
        const float tk = sak[k];
        float P[4][4];
#pragma unroll
        for (int j = 0; j < 4; j++) {
            P[j][0] = sc[j + k - 3];
            P[j][1] = P[j][2] = P[j][3] = 0.0f;
        }
#pragma unroll
        for (int r = 1; r <= 3; r++) {
#pragma unroll
            for (int j = 3; j >= 1; j--) {
                if (j < r) continue;
                float ta = sak[j + k - 3];
                float tb = sak[j + 1 + k - r];
                float rcp = 1.0f / (tb - ta);
                float A = (tk - ta) * rcp;   // alpha = A + B*u
                float B = rcp;
                float q0 = (1.0f - A) * P[j - 1][0] + A * P[j][0];
                float q1 = (1.0f - A) * P[j - 1][1] + A * P[j][1]
                         + B * (P[j][0] - P[j - 1][0]);
                float q2 = (1.0f - A) * P[j - 1][2] + A * P[j][2]
                         + B * (P[j][1] - P[j - 1][1]);
                float q3 = (1.0f - A) * P[j - 1][3] + A * P[j][3]
                         + B * (P[j][2] - P[j - 1][2]);
                P[j][0] = q0; P[j][1] = q1; P[j][2] = q2; P[j][3] = q3;
            }
        }
        dP[tid][0] = P[3][0]; dP[tid][1] = P[3][1];
        dP[tid][2] = P[3][2]; dP[tid][3] = P[3][3];
    }
    __syncthreads();

    // ---- linear table over x in [0,1): 2048 cells ----
    {
        const float invT = 1.0f / (float)NSFF_T;
#pragma unroll
        for (int m = 0; m < NSFF_T / 256; m++) {
            int j = tid + m * 256;
            float xl = (float)j * invT;
            float xr = (float)(j + 1) * invT;
            float f0 = nsff_spline_eval(xl, sak, dP);
            float f1 = nsff_spline_eval(xr, sak, dP);
            tab[j] = make_float2(f0, f1 - f0);
        }
    }
    __syncthreads();

    // ---- streaming main loop ----
    const float4* __restrict__ x4 = reinterpret_cast<const float4*>(x);
    float4* __restrict__ o4 = reinterpret_cast<float4*>(out);

    const int nth = gridDim.x * blockDim.x;
    int i = blockIdx.x * blockDim.x + tid;

    // fast path: 4 float4 per iteration, no predicates
    for (; i + 3 * nth < n4; i += 4 * nth) {
        float4 v0 = x4[i];                    // allocating load: x owns L2
        float4 v1 = x4[i + nth];
        float4 v2 = x4[i + 2 * nth];
        float4 v3 = x4[i + 3 * nth];
        float4 r0, r1, r2, r3;
        r0.x = nsff_lookup(v0.x, tab); r0.y = nsff_lookup(v0.y, tab);
        r0.z = nsff_lookup(v0.z, tab); r0.w = nsff_lookup(v0.w, tab);
        r1.x = nsff_lookup(v1.x, tab); r1.y = nsff_lookup(v1.y, tab);
        r1.z = nsff_lookup(v1.z, tab); r1.w = nsff_lookup(v1.w, tab);
        r2.x = nsff_lookup(v2.x, tab); r2.y = nsff_lookup(v2.y, tab);
        r2.z = nsff_lookup(v2.z, tab); r2.w = nsff_lookup(v2.w, tab);
        r3.x = nsff_lookup(v3.x, tab); r3.y = nsff_lookup(v3.y, tab);
        r3.z = nsff_lookup(v3.z, tab); r3.w = nsff_lookup(v3.w, tab);
        __stwt(&o4[i], r0);                   // write-through: no L2 claim
        __stwt(&o4[i + nth], r1);
        __stwt(&o4[i + 2 * nth], r2);
        __stwt(&o4[i + 3 * nth], r3);
    }
    // tail
    for (; i < n4; i += nth) {
        float4 v = x4[i];
        float4 r;
        r.x = nsff_lookup(v.x, tab);
        r.y = nsff_lookup(v.y, tab);
        r.z = nsff_lookup(v.z, tab);
        r.w = nsff_lookup(v.w, tab);
        __stwt(&o4[i], r);
    }
}

extern "C" void kernel_launch(void* const* d_in, const int* in_sizes, int n_in,
                              void* d_out, int out_size) {
    const float* x  = (const float*)d_in[0];
    const float* a  = (const float*)d_in[1];
    const float* W1 = (const float*)d_in[2];
    const float* b1 = (const float*)d_in[3];
    const float* W2 = (const float*)d_in[4];
    const float* b2 = (const float*)d_in[5];
    const float* Ww = (const float*)d_in[6];
    const float* bw = (const float*)d_in[7];
    const float* Wk = (const float*)d_in[8];
    const float* bk = (const float*)d_in[9];
    float* out = (float*)d_out;

    const int n4 = out_size / 4;   // 4,194,304 for 256^3
    int blocks = 152 * 6;          // persistent: 6 blocks/SM, 16KB table each
    int need = (n4 + 255) / 256;
    if (blocks > need) blocks = need;
    nsff_fused_kernel<<<blocks, 256>>>(x, a, W1, b1, W2, b2, Ww, bw, Wk, bk,
                                       out, n4);
}

// round 10
// speedup vs baseline: 1.0106x; 1.0106x over previous
#include <cuda_runtime.h>
#include <math.h>
#include <stdint.h>

// -----------------------------------------------------------------------------
// NeuralSplineFourierFilter — fused persistent kernel + explicit L2 policies.
//
// Evidence through r9: DRAM/replay ~82MB = 64MB out-writebacks + ~18MB x
// read-misses; combined BW pinned ~4.4TB/s. x (64MB, identical every replay)
// should be fully L2-resident (L2=126MB); the thing evicting it is out's 64MB
// store stream. Plain .cs hints can't separate the two streams strongly
// enough; __stwt (r9) was a disaster (serialized DRAM writes, 45.6us).
//
// This round: PTX createpolicy-based cache hints (graph-safe, in-kernel):
//   x loads:  L2::cache_hint with evict_last  (pin x across graph replays)
//   out stores: L2::cache_hint with evict_first (stream, don't thrash x)
// Everything else identical to the 29.2us best (r5): 2048-cell linear table
// (16KB smem, rel_err 1.4e-6), 912 blocks x 256 threads, 4x float4 loop.
// -----------------------------------------------------------------------------

#define NSFF_T 2048
#define NSFF_RSQRT3F 0.57735026918962576f

__device__ __forceinline__ float nsff_spline_eval(
    float xe, const float* __restrict__ sak, const float (*__restrict__ dP)[4]) {
    float xp = fminf(fmaxf(xe * NSFF_RSQRT3F, 0.0f), 0.9999f);
    int i = (xp >= sak[4]) + (xp >= sak[5]) + (xp >= sak[6])
          + (xp >= sak[7]) + (xp >= sak[8]) + (xp >= sak[9]);
    float u = xp - sak[3 + i];
    return fmaf(fmaf(fmaf(dP[i][3], u, dP[i][2]), u, dP[i][1]), u, dP[i][0]);
}

__device__ __forceinline__ float nsff_lookup(float xx, const float2* __restrict__ tab) {
    float y = xx * (float)NSFF_T;     // x in [0,1) -> y in [0,2048)
    int j = (int)y;
    float t = y - (float)j;
    float2 c = tab[j];
    return fmaf(t, c.y, c.x);
}

// --- L2 policy helpers (PTX createpolicy + cache_hint memory ops) ---

__device__ __forceinline__ uint64_t nsff_policy_evict_last() {
    uint64_t pol;
    asm("createpolicy.fractional.L2::evict_last.b64 %0, 1.0;" : "=l"(pol));
    return pol;
}

__device__ __forceinline__ uint64_t nsff_policy_evict_first() {
    uint64_t pol;
    asm("createpolicy.fractional.L2::evict_first.b64 %0, 1.0;" : "=l"(pol));
    return pol;
}

__device__ __forceinline__ float4 nsff_ld_pinned(const float4* p, uint64_t pol) {
    float4 v;
    asm volatile("ld.global.L2::cache_hint.v4.f32 {%0,%1,%2,%3}, [%4], %5;"
                 : "=f"(v.x), "=f"(v.y), "=f"(v.z), "=f"(v.w)
                 : "l"(p), "l"(pol));
    return v;
}

__device__ __forceinline__ void nsff_st_stream(float4* p, float4 v, uint64_t pol) {
    asm volatile("st.global.L2::cache_hint.v4.f32 [%0], {%1,%2,%3,%4}, %5;"
                 :: "l"(p), "f"(v.x), "f"(v.y), "f"(v.z), "f"(v.w), "l"(pol)
                 : "memory");
}

__global__ void __launch_bounds__(256, 6)
nsff_fused_kernel(const float* __restrict__ x,
                  const float* __restrict__ a,
                  const float* __restrict__ W1,
                  const float* __restrict__ b1,
                  const float* __restrict__ W2,
                  const float* __restrict__ b2,
                  const float* __restrict__ Ww,
                  const float* __restrict__ bw,
                  const float* __restrict__ Wk,
                  const float* __restrict__ bk,
                  float* __restrict__ out, int n4) {
    __shared__ float net1[32];
    __shared__ float net2[32];
    __shared__ float sw[9];
    __shared__ float skraw[7];
    __shared__ float sak[14];
    __shared__ float sc[10];
    __shared__ float dP[7][4];
    __shared__ __align__(8) float2 tab[NSFF_T];

    const int tid = threadIdx.x;

    // ---- tiny MLP (warp 0) ----
    if (tid < 32) {
        float av = a[0];
        net1[tid] = sinf(av * W1[tid] + b1[tid]);
    }
    __syncthreads();
    if (tid < 32) {
        float acc = b2[tid];
#pragma unroll
        for (int j = 0; j < 32; j++) acc += net1[j] * W2[j * 32 + tid];
        net2[tid] = sinf(acc);
    }
    __syncthreads();
    if (tid < 9) {
        float s = bw[tid];
#pragma unroll
        for (int j = 0; j < 32; j++) s += net2[j] * Ww[j * 9 + tid];
        sw[tid] = s;
    }
    if (tid < 7) {
        float s = bk[tid];
#pragma unroll
        for (int j = 0; j < 32; j++) s += net2[j] * Wk[j * 7 + tid];
        skraw[tid] = s;
    }
    __syncthreads();

    // ---- softmax + cumsum -> knot vector; control points (lane 0) ----
    if (tid == 0) {
        float m = skraw[0];
#pragma unroll
        for (int j = 1; j < 7; j++) m = fmaxf(m, skraw[j]);
        float e[7];
        float tot = 0.0f;
#pragma unroll
        for (int j = 0; j < 7; j++) { e[j] = expf(skraw[j] - m); tot += e[j]; }
        float inv = 1.0f / tot;

        sak[0] = sak[1] = sak[2] = 0.0f;
        sak[3] = 0.0f;
        float cum = 0.0f;
#pragma unroll
        for (int j = 0; j < 7; j++) { cum += e[j] * inv; sak[4 + j] = cum; }
        sak[11] = sak[12] = sak[13] = 1.0f;

        sc[0] = 0.0f;
#pragma unroll
        for (int j = 0; j < 9; j++) sc[1 + j] = sw[j];
    }
    __syncthreads();

    // ---- symbolic de Boor per interval k = 3 + lane, in u = xp - ak[k] ----
    if (tid < 7) {
        const int k = 3 + tid;
        const float tk = sak[k];
        float P[4][4];
#pragma unroll
        for (int j = 0; j < 4; j++) {
            P[j][0] = sc[j + k - 3];
            P[j][1] = P[j][2] = P[j][3] = 0.0f;
        }
#pragma unroll
        for (int r = 1; r <= 3; r++) {
#pragma unroll
            for (int j = 3; j >= 1; j--) {
                if (j < r) continue;
                float ta = sak[j + k - 3];
                float tb = sak[j + 1 + k - r];
                float rcp = 1.0f / (tb - ta);
                float A = (tk - ta) * rcp;   // alpha = A + B*u
                float B = rcp;
                float q0 = (1.0f - A) * P[j - 1][0] + A * P[j][0];
                float q1 = (1.0f - A) * P[j - 1][1] + A * P[j][1]
                         + B * (P[j][0] - P[j - 1][0]);
                float q2 = (1.0f - A) * P[j - 1][2] + A * P[j][2]
                         + B * (P[j][1] - P[j - 1][1]);
                float q3 = (1.0f - A) * P[j - 1][3] + A * P[j][3]
                         + B * (P[j][2] - P[j - 1][2]);
                P[j][0] = q0; P[j][1] = q1; P[j][2] = q2; P[j][3] = q3;
            }
        }
        dP[tid][0] = P[3][0]; dP[tid][1] = P[3][1];
        dP[tid][2] = P[3][2]; dP[tid][3] = P[3][3];
    }
    __syncthreads();

    // ---- linear table over x in [0,1): 2048 cells ----
    {
        const float invT = 1.0f / (float)NSFF_T;
#pragma unroll
        for (int m = 0; m < NSFF_T / 256; m++) {
            int j = tid + m * 256;
            float xl = (float)j * invT;
            float xr = (float)(j + 1) * invT;
            float f0 = nsff_spline_eval(xl, sak, dP);
            float f1 = nsff_spline_eval(xr, sak, dP);
            tab[j] = make_float2(f0, f1 - f0);
        }
    }
    __syncthreads();

    // ---- streaming main loop ----
    const float4* __restrict__ x4 = reinterpret_cast<const float4*>(x);
    float4* __restrict__ o4 = reinterpret_cast<float4*>(out);

    const uint64_t pol_ld = nsff_policy_evict_last();   // pin x in L2
    const uint64_t pol_st = nsff_policy_evict_first();  // stream out

    const int nth = gridDim.x * blockDim.x;
    int i = blockIdx.x * blockDim.x + tid;

    // fast path: 4 float4 per iteration, no predicates
    for (; i + 3 * nth < n4; i += 4 * nth) {
        float4 v0 = nsff_ld_pinned(&x4[i], pol_ld);
        float4 v1 = nsff_ld_pinned(&x4[i + nth], pol_ld);
        float4 v2 = nsff_ld_pinned(&x4[i + 2 * nth], pol_ld);
        float4 v3 = nsff_ld_pinned(&x4[i + 3 * nth], pol_ld);
        float4 r0, r1, r2, r3;
        r0.x = nsff_lookup(v0.x, tab); r0.y = nsff_lookup(v0.y, tab);
        r0.z = nsff_lookup(v0.z, tab); r0.w = nsff_lookup(v0.w, tab);
        r1.x = nsff_lookup(v1.x, tab); r1.y = nsff_lookup(v1.y, tab);
        r1.z = nsff_lookup(v1.z, tab); r1.w = nsff_lookup(v1.w, tab);
        r2.x = nsff_lookup(v2.x, tab); r2.y = nsff_lookup(v2.y, tab);
        r2.z = nsff_lookup(v2.z, tab); r2.w = nsff_lookup(v2.w, tab);
        r3.x = nsff_lookup(v3.x, tab); r3.y = nsff_lookup(v3.y, tab);
        r3.z = nsff_lookup(v3.z, tab); r3.w = nsff_lookup(v3.w, tab);
        nsff_st_stream(&o4[i], r0, pol_st);
        nsff_st_stream(&o4[i + nth], r1, pol_st);
        nsff_st_stream(&o4[i + 2 * nth], r2, pol_st);
        nsff_st_stream(&o4[i + 3 * nth], r3, pol_st);
    }
    // tail
    for (; i < n4; i += nth) {
        float4 v = nsff_ld_pinned(&x4[i], pol_ld);
        float4 r;
        r.x = nsff_lookup(v.x, tab);
        r.y = nsff_lookup(v.y, tab);
        r.z = nsff_lookup(v.z, tab);
        r.w = nsff_lookup(v.w, tab);
        nsff_st_stream(&o4[i], r, pol_st);
    }
}

extern "C" void kernel_launch(void* const* d_in, const int* in_sizes, int n_in,
                              void* d_out, int out_size) {
    const float* x  = (const float*)d_in[0];
    const float* a  = (const float*)d_in[1];
    const float* W1 = (const float*)d_in[2];
    const float* b1 = (const float*)d_in[3];
    const float* W2 = (const float*)d_in[4];
    const float* b2 = (const float*)d_in[5];
    const float* Ww = (const float*)d_in[6];
    const float* bw = (const float*)d_in[7];
    const float* Wk = (const float*)d_in[8];
    const float* bk = (const float*)d_in[9];
    float* out = (float*)d_out;

    const int n4 = out_size / 4;   // 4,194,304 for 256^3
    int blocks = 152 * 6;          // persistent: 6 blocks/SM, 16KB table each
    int need = (n4 + 255) / 256;
    if (blocks > need) blocks = need;
    nsff_fused_kernel<<<blocks, 256>>>(x, a, W1, b1, W2, b2, Ww, bw, Wk, bk,
                                       out, n4);
}

// round 11
// speedup vs baseline: 1.4615x; 1.4462x over previous
#include <cuda_runtime.h>
#include <math.h>

// -----------------------------------------------------------------------------
// NeuralSplineFourierFilter — r5 best (29.2us) + 256-bit global ld/st.
//
// r9/r10 exhausted the L2-policy space: (.cs loads + .cs stores) is the proven
// best pair; aggressive policies (wt, evict_last pin) regress badly. This round
// keeps r5 byte-identical EXCEPT the global accesses use Blackwell 256-bit
// vectors (ld/st.global.cs.v8.f32): same bytes, same hints, same 64B/thread in
// flight, half the LDG/STG instructions and LSU dispatch slots.
//
// Table: 2048-cell linear-interp float2 {f, df} over x in [0,1), 16KB smem,
// built per block from symbolically expanded de Boor cubics (rel_err 1.4e-6).
// Grid 912 x 256 persistent (6 blocks/SM).
// -----------------------------------------------------------------------------

#define NSFF_T 2048
#define NSFF_RSQRT3F 0.57735026918962576f

__device__ __forceinline__ float nsff_spline_eval(
    float xe, const float* __restrict__ sak, const float (*__restrict__ dP)[4]) {
    float xp = fminf(fmaxf(xe * NSFF_RSQRT3F, 0.0f), 0.9999f);
    int i = (xp >= sak[4]) + (xp >= sak[5]) + (xp >= sak[6])
          + (xp >= sak[7]) + (xp >= sak[8]) + (xp >= sak[9]);
    float u = xp - sak[3 + i];
    return fmaf(fmaf(fmaf(dP[i][3], u, dP[i][2]), u, dP[i][1]), u, dP[i][0]);
}

__device__ __forceinline__ float nsff_lookup(float xx, const float2* __restrict__ tab) {
    float y = xx * (float)NSFF_T;     // x in [0,1) -> y in [0,2048)
    int j = (int)y;
    float t = y - (float)j;
    float2 c = tab[j];
    return fmaf(t, c.y, c.x);
}

// ---- 256-bit global memory ops (sm_100+), streaming (.cs) hint ----
__device__ __forceinline__ void nsff_ld8_cs(const float* p, float* v) {
    asm volatile("ld.global.cs.v8.f32 {%0,%1,%2,%3,%4,%5,%6,%7}, [%8];"
                 : "=f"(v[0]), "=f"(v[1]), "=f"(v[2]), "=f"(v[3]),
                   "=f"(v[4]), "=f"(v[5]), "=f"(v[6]), "=f"(v[7])
                 : "l"(p));
}

__device__ __forceinline__ void nsff_st8_cs(float* p, const float* v) {
    asm volatile("st.global.cs.v8.f32 [%0], {%1,%2,%3,%4,%5,%6,%7,%8};"
                 :: "l"(p),
                    "f"(v[0]), "f"(v[1]), "f"(v[2]), "f"(v[3]),
                    "f"(v[4]), "f"(v[5]), "f"(v[6]), "f"(v[7])
                 : "memory");
}

__global__ void __launch_bounds__(256, 6)
nsff_fused_kernel(const float* __restrict__ x,
                  const float* __restrict__ a,
                  const float* __restrict__ W1,
                  const float* __restrict__ b1,
                  const float* __restrict__ W2,
                  const float* __restrict__ b2,
                  const float* __restrict__ Ww,
                  const float* __restrict__ bw,
                  const float* __restrict__ Wk,
                  const float* __restrict__ bk,
                  float* __restrict__ out, int n8) {
    __shared__ float net1[32];
    __shared__ float net2[32];
    __shared__ float sw[9];
    __shared__ float skraw[7];
    __shared__ float sak[14];
    __shared__ float sc[10];
    __shared__ float dP[7][4];
    __shared__ __align__(8) float2 tab[NSFF_T];

    const int tid = threadIdx.x;

    // ---- tiny MLP (warp 0) ----
    if (tid < 32) {
        float av = a[0];
        net1[tid] = sinf(av * W1[tid] + b1[tid]);
    }
    __syncthreads();
    if (tid < 32) {
        float acc = b2[tid];
#pragma unroll
        for (int j = 0; j < 32; j++) acc += net1[j] * W2[j * 32 + tid];
        net2[tid] = sinf(acc);
    }
    __syncthreads();
    if (tid < 9) {
        float s = bw[tid];
#pragma unroll
        for (int j = 0; j < 32; j++) s += net2[j] * Ww[j * 9 + tid];
        sw[tid] = s;
    }
    if (tid < 7) {
        float s = bk[tid];
#pragma unroll
        for (int j = 0; j < 32; j++) s += net2[j] * Wk[j * 7 + tid];
        skraw[tid] = s;
    }
    __syncthreads();

    // ---- softmax + cumsum -> knot vector; control points (lane 0) ----
    if (tid == 0) {
        float m = skraw[0];
#pragma unroll
        for (int j = 1; j < 7; j++) m = fmaxf(m, skraw[j]);
        float e[7];
        float tot = 0.0f;
#pragma unroll
        for (int j = 0; j < 7; j++) { e[j] = expf(skraw[j] - m); tot += e[j]; }
        float inv = 1.0f / tot;

        sak[0] = sak[1] = sak[2] = 0.0f;
        sak[3] = 0.0f;
        float cum = 0.0f;
#pragma unroll
        for (int j = 0; j < 7; j++) { cum += e[j] * inv; sak[4 + j] = cum; }
        sak[11] = sak[12] = sak[13] = 1.0f;

        sc[0] = 0.0f;
#pragma unroll
        for (int j = 0; j < 9; j++) sc[1 + j] = sw[j];
    }
    __syncthreads();

    // ---- symbolic de Boor per interval k = 3 + lane, in u = xp - ak[k] ----
    if (tid < 7) {
        const int k = 3 + tid;
        const float tk = sak[k];
        float P[4][4];
#pragma unroll
        for (int j = 0; j < 4; j++) {
            P[j][0] = sc[j + k - 3];
            P[j][1] = P[j][2] = P[j][3] = 0.0f;
        }
#pragma unroll
        for (int r = 1; r <= 3; r++) {
#pragma unroll
            for (int j = 3; j >= 1; j--) {
                if (j < r) continue;
                float ta = sak[j + k - 3];
                float tb = sak[j + 1 + k - r];
                float rcp = 1.0f / (tb - ta);
                float A = (tk - ta) * rcp;   // alpha = A + B*u
                float B = rcp;
                float q0 = (1.0f - A) * P[j - 1][0] + A * P[j][0];
                float q1 = (1.0f - A) * P[j - 1][1] + A * P[j][1]
                         + B * (P[j][0] - P[j - 1][0]);
                float q2 = (1.0f - A) * P[j - 1][2] + A * P[j][2]
                         + B * (P[j][1] - P[j - 1][1]);
                float q3 = (1.0f - A) * P[j - 1][3] + A * P[j][3]
                         + B * (P[j][2] - P[j - 1][2]);
                P[j][0] = q0; P[j][1] = q1; P[j][2] = q2; P[j][3] = q3;
            }
        }
        dP[tid][0] = P[3][0]; dP[tid][1] = P[3][1];
        dP[tid][2] = P[3][2]; dP[tid][3] = P[3][3];
    }
    __syncthreads();

    // ---- linear table over x in [0,1): 2048 cells ----
    {
        const float invT = 1.0f / (float)NSFF_T;
#pragma unroll
        for (int m = 0; m < NSFF_T / 256; m++) {
            int j = tid + m * 256;
            float xl = (float)j * invT;
            float xr = (float)(j + 1) * invT;
            float f0 = nsff_spline_eval(xl, sak, dP);
            float f1 = nsff_spline_eval(xr, sak, dP);
            tab[j] = make_float2(f0, f1 - f0);
        }
    }
    __syncthreads();

    // ---- streaming main loop: float8 (32B) units ----
    const int nth = gridDim.x * blockDim.x;
    int i = blockIdx.x * blockDim.x + tid;

    // fast path: 2 x 32B per iteration (64B/thread in flight, as r5)
    for (; i + nth < n8; i += 2 * nth) {
        float v0[8], v1[8];
        nsff_ld8_cs(x + (size_t)i * 8, v0);
        nsff_ld8_cs(x + (size_t)(i + nth) * 8, v1);
        float r0[8], r1[8];
#pragma unroll
        for (int m = 0; m < 8; m++) r0[m] = nsff_lookup(v0[m], tab);
#pragma unroll
        for (int m = 0; m < 8; m++) r1[m] = nsff_lookup(v1[m], tab);
        nsff_st8_cs(out + (size_t)i * 8, r0);
        nsff_st8_cs(out + (size_t)(i + nth) * 8, r1);
    }
    // tail: single 32B per step
    for (; i < n8; i += nth) {
        float v[8], r[8];
        nsff_ld8_cs(x + (size_t)i * 8, v);
#pragma unroll
        for (int m = 0; m < 8; m++) r[m] = nsff_lookup(v[m], tab);
        nsff_st8_cs(out + (size_t)i * 8, r);
    }
}

extern "C" void kernel_launch(void* const* d_in, const int* in_sizes, int n_in,
                              void* d_out, int out_size) {
    const float* x  = (const float*)d_in[0];
    const float* a  = (const float*)d_in[1];
    const float* W1 = (const float*)d_in[2];
    const float* b1 = (const float*)d_in[3];
    const float* W2 = (const float*)d_in[4];
    const float* b2 = (const float*)d_in[5];
    const float* Ww = (const float*)d_in[6];
    const float* bw = (const float*)d_in[7];
    const float* Wk = (const float*)d_in[8];
    const float* bk = (const float*)d_in[9];
    float* out = (float*)d_out;

    const int n8 = out_size / 8;   // 2,097,152 for 256^3 (32B-aligned units)
    int blocks = 152 * 6;          // persistent: 6 blocks/SM, 16KB table each
    int need = (n8 + 255) / 256;
    if (blocks > need) blocks = need;
    nsff_fused_kernel<<<blocks, 256>>>(x, a, W1, b1, W2, b2, Ww, bw, Wk, bk,
                                       out, n8);
}